// round 2
// baseline (speedup 1.0000x reference)
#include <cuda_runtime.h>
#include <cstdint>

#define N_NODES 50000
#define N_EDGES 160000
#define DIM     512
#define N_GRAPHS 64
#define EPSV    1e-5f

// ---- scratch (static __device__: allocation-free) ----
__device__ float g_xw [(size_t)N_NODES * DIM];   // x @ W
__device__ float g_acc[(size_t)N_NODES * DIM];   // node + b + conv (accumulator)
__device__ float g_deg[N_NODES];
__device__ float g_sum[N_GRAPHS * DIM];
__device__ float g_var[N_GRAPHS * DIM];
__device__ float g_cnt[N_GRAPHS];
__device__ int   g_ei_row[N_EDGES];              // canonical int32 source ids
__device__ int   g_ei_col[N_EDGES];              // canonical int32 target ids
__device__ int   g_batch [N_NODES];              // canonical int32 graph ids

// ---------------------------------------------------------------- dtype-robust index conversion
// JAX without x64 silently coerces the reference's int64 indices to int32.
// Detect which dtype we actually got: genuine int64 node ids are all < N_NODES;
// int32 data read as int64 gives lo + hi*2^32 with hi a random node id (never
// all-zero across 8 probes). One flag covers edge_index and batch_ptr.
__global__ void k_convert(const void* __restrict__ ei, const void* __restrict__ batch) {
    __shared__ int s64;
    const int tid = threadIdx.x;
    if (tid == 0) {
        const long long* q = (const long long*)ei;
        int ok = 1;
#pragma unroll
        for (int i = 0; i < 8; i++) {
            long long v = q[i];
            if (v < 0 || v >= N_NODES) ok = 0;
        }
        s64 = ok;
    }
    __syncthreads();
    const int is64 = s64;
    const int e = blockIdx.x * blockDim.x + tid;
    if (e < N_EDGES) {
        int r, c;
        if (is64) {
            r = (int)((const long long*)ei)[e];
            c = (int)((const long long*)ei)[N_EDGES + e];
        } else {
            r = ((const int*)ei)[e];
            c = ((const int*)ei)[N_EDGES + e];
        }
        g_ei_row[e] = min(max(r, 0), N_NODES - 1);
        g_ei_col[e] = min(max(c, 0), N_NODES - 1);
    }
    if (e < N_NODES) {
        int bv = is64 ? (int)((const long long*)batch)[e] : ((const int*)batch)[e];
        g_batch[e] = min(max(bv, 0), N_GRAPHS - 1);
    }
}

// ---------------------------------------------------------------- init
__global__ void k_init() {
    int i = blockIdx.x * blockDim.x + threadIdx.x;
    if (i < N_NODES) g_deg[i] = 1.0f;               // self-loop weight
    if (i < N_GRAPHS * DIM) { g_sum[i] = 0.f; g_var[i] = 0.f; }
    if (i < N_GRAPHS) g_cnt[i] = 0.f;
}

// ---------------------------------------------------------------- degree
__global__ void k_deg(const float* __restrict__ w) {
    int e = blockIdx.x * blockDim.x + threadIdx.x;
    if (e < N_EDGES) atomicAdd(&g_deg[g_ei_col[e]], w[e]);
}

// ---------------------------------------------------------------- tf32 helpers
__device__ __forceinline__ float tf32f(float x) {
    uint32_t r;
    asm("cvt.rna.tf32.f32 %0, %1;" : "=r"(r) : "f"(x));
    return __uint_as_float(r);
}
__device__ __forceinline__ void mma_tf32(float* d, const uint32_t* a, const uint32_t* b) {
    asm volatile(
        "mma.sync.aligned.m16n8k8.row.col.f32.tf32.tf32.f32 "
        "{%0,%1,%2,%3},{%4,%5,%6,%7},{%8,%9},{%0,%1,%2,%3};\n"
        : "+f"(d[0]), "+f"(d[1]), "+f"(d[2]), "+f"(d[3])
        : "r"(a[0]), "r"(a[1]), "r"(a[2]), "r"(a[3]), "r"(b[0]), "r"(b[1]));
}

// ---------------------------------------------------------------- GEMM + fused epilogue
// C = node @ W  (M=50000, N=512, K=512), tf32.  BM=128 BN=128 BK=16, 8 warps (2x4),
// warp tile 64x32, mma m16n8k8 grid 4x4.  Epilogue writes g_xw and
// g_acc = node + b + xw/deg (skip + bias + self-loop term).
#define AS_STR 20
#define BS_STR 136
__global__ __launch_bounds__(256) void k_gemm(
    const float* __restrict__ A,      // node [M,512]
    const float* __restrict__ B,      // W [512,512]
    const float* __restrict__ bias)   // b [512]
{
    __shared__ float As[2][128 * AS_STR];
    __shared__ float Bs[2][16 * BS_STR];
    const int tid  = threadIdx.x;
    const int lane = tid & 31;
    const int warp = tid >> 5;
    const int wm = warp >> 2;   // 0..1
    const int wn = warp & 3;    // 0..3
    const int m0 = blockIdx.y * 128;
    const int n0 = blockIdx.x * 128;

    const int ar  = tid >> 2;   // 0..63 (A rows; +64 for second element)
    const int ac4 = tid & 3;    // A float4 column
    const int br0 = tid >> 5;   // 0..7 (B rows; +8 for second)
    const int bc4 = tid & 31;   // B float4 column

    float acc[4][4][4];
#pragma unroll
    for (int i = 0; i < 4; i++)
#pragma unroll
        for (int j = 0; j < 4; j++)
#pragma unroll
            for (int c = 0; c < 4; c++) acc[i][j][c] = 0.f;

    float4 av0, av1, bv0, bv1;

#define LOAD_TILES(KT) do {                                                    \
        int kk = (KT) * 16;                                                    \
        int gm0 = m0 + ar, gm1 = gm0 + 64;                                     \
        const float* ap = A + kk + ac4 * 4;                                    \
        av0 = (gm0 < N_NODES) ? *(const float4*)(ap + (size_t)gm0 * 512)       \
                              : make_float4(0.f,0.f,0.f,0.f);                  \
        av1 = (gm1 < N_NODES) ? *(const float4*)(ap + (size_t)gm1 * 512)       \
                              : make_float4(0.f,0.f,0.f,0.f);                  \
        const float* bp = B + n0 + bc4 * 4;                                    \
        bv0 = *(const float4*)(bp + (size_t)(kk + br0) * 512);                 \
        bv1 = *(const float4*)(bp + (size_t)(kk + br0 + 8) * 512);             \
    } while (0)

#define STORE_TILES(BUF) do {                                                  \
        float* a0 = &As[BUF][ar * AS_STR + ac4 * 4];                           \
        a0[0]=tf32f(av0.x); a0[1]=tf32f(av0.y); a0[2]=tf32f(av0.z); a0[3]=tf32f(av0.w); \
        float* a1 = &As[BUF][(ar + 64) * AS_STR + ac4 * 4];                    \
        a1[0]=tf32f(av1.x); a1[1]=tf32f(av1.y); a1[2]=tf32f(av1.z); a1[3]=tf32f(av1.w); \
        float* b0 = &Bs[BUF][br0 * BS_STR + bc4 * 4];                          \
        b0[0]=tf32f(bv0.x); b0[1]=tf32f(bv0.y); b0[2]=tf32f(bv0.z); b0[3]=tf32f(bv0.w); \
        float* b1 = &Bs[BUF][(br0 + 8) * BS_STR + bc4 * 4];                    \
        b1[0]=tf32f(bv1.x); b1[1]=tf32f(bv1.y); b1[2]=tf32f(bv1.z); b1[3]=tf32f(bv1.w); \
    } while (0)

    LOAD_TILES(0);
    STORE_TILES(0);
    __syncthreads();

#pragma unroll 1
    for (int kt = 0; kt < 32; kt++) {
        const int buf = kt & 1;
        if (kt < 31) LOAD_TILES(kt + 1);
        const float* as = As[buf];
        const float* bs = Bs[buf];
#pragma unroll
        for (int ks = 0; ks < 2; ks++) {
            uint32_t af[4][4], bf[4][2];
            const int kk = ks * 8 + (lane & 3);
#pragma unroll
            for (int i = 0; i < 4; i++) {
                int r = wm * 64 + i * 16 + (lane >> 2);
                af[i][0] = __float_as_uint(as[r * AS_STR + kk]);
                af[i][1] = __float_as_uint(as[(r + 8) * AS_STR + kk]);
                af[i][2] = __float_as_uint(as[r * AS_STR + kk + 4]);
                af[i][3] = __float_as_uint(as[(r + 8) * AS_STR + kk + 4]);
            }
#pragma unroll
            for (int j = 0; j < 4; j++) {
                int c = wn * 32 + j * 8 + (lane >> 2);
                bf[j][0] = __float_as_uint(bs[kk * BS_STR + c]);
                bf[j][1] = __float_as_uint(bs[(kk + 4) * BS_STR + c]);
            }
#pragma unroll
            for (int i = 0; i < 4; i++)
#pragma unroll
                for (int j = 0; j < 4; j++)
                    mma_tf32(acc[i][j], af[i], bf[j]);
        }
        if (kt < 31) STORE_TILES(buf ^ 1);
        __syncthreads();
    }

    // epilogue: xw -> g_xw ; g_acc = node + b + xw/deg
#pragma unroll
    for (int i = 0; i < 4; i++) {
        const int rbase = m0 + wm * 64 + i * 16 + (lane >> 2);
#pragma unroll
        for (int h = 0; h < 2; h++) {
            const int gm = rbase + h * 8;
            if (gm < N_NODES) {
                const float invdeg = 1.0f / g_deg[gm];
#pragma unroll
                for (int j = 0; j < 4; j++) {
                    const int cb = n0 + wn * 32 + j * 8 + ((lane & 3) << 1);
                    const size_t o = (size_t)gm * 512 + cb;
                    const float v0 = acc[i][j][h * 2 + 0];
                    const float v1 = acc[i][j][h * 2 + 1];
                    g_xw[o] = v0;  g_xw[o + 1] = v1;
                    g_acc[o]     = A[o]     + bias[cb]     + v0 * invdeg;
                    g_acc[o + 1] = A[o + 1] + bias[cb + 1] + v1 * invdeg;
                }
            }
        }
    }
#undef LOAD_TILES
#undef STORE_TILES
}

// ---------------------------------------------------------------- edge scatter
// one block (128 threads) per edge; float4 vector atomics
__global__ __launch_bounds__(128) void k_scatter(const float* __restrict__ w) {
    const int e = blockIdx.x;
    const int r = g_ei_row[e];
    const int c = g_ei_col[e];
    const float coef = w[e] * rsqrtf(g_deg[r]) * rsqrtf(g_deg[c]);
    const float4* src = (const float4*)(g_xw + (size_t)r * DIM);
    float4* dst = (float4*)(g_acc + (size_t)c * DIM);
    const int t = threadIdx.x;
    float4 v = src[t];
    asm volatile("red.global.add.v4.f32 [%0], {%1,%2,%3,%4};"
                 :: "l"(dst + t), "f"(v.x * coef), "f"(v.y * coef),
                    "f"(v.z * coef), "f"(v.w * coef)
                 : "memory");
}

// ---------------------------------------------------------------- GraphNorm pass 1: sums + counts
// batch is sorted -> contiguous graph runs; local accumulate, atomic on transitions.
__global__ __launch_bounds__(256) void k_stats1() {
    const int n0 = blockIdx.x * 128;
    const int nend = min(n0 + 128, N_NODES);
    const int t = threadIdx.x;
    const int d0 = t, d1 = t + 256;
    float s0 = 0.f, s1 = 0.f;
    int g = g_batch[n0], cnt = 0;
    for (int n = n0; n < nend; n++) {
        const int gn = g_batch[n];
        if (gn != g) {
            atomicAdd(&g_sum[g * DIM + d0], s0);
            atomicAdd(&g_sum[g * DIM + d1], s1);
            if (t == 0) atomicAdd(&g_cnt[g], (float)cnt);
            s0 = 0.f; s1 = 0.f; cnt = 0; g = gn;
        }
        const float* row = g_acc + (size_t)n * DIM;
        s0 += row[d0]; s1 += row[d1]; cnt++;
    }
    atomicAdd(&g_sum[g * DIM + d0], s0);
    atomicAdd(&g_sum[g * DIM + d1], s1);
    if (t == 0) atomicAdd(&g_cnt[g], (float)cnt);
}

// ---------------------------------------------------------------- GraphNorm pass 2: variance
__global__ __launch_bounds__(256) void k_stats2(const float* __restrict__ ms) {
    const int n0 = blockIdx.x * 128;
    const int nend = min(n0 + 128, N_NODES);
    const int t = threadIdx.x;
    const int d0 = t, d1 = t + 256;
    const float ms0 = ms[d0], ms1 = ms[d1];
    int g = g_batch[n0];
    float ic = 1.f / fmaxf(g_cnt[g], 1.f);
    float m0v = g_sum[g * DIM + d0] * ic * ms0;
    float m1v = g_sum[g * DIM + d1] * ic * ms1;
    float s0 = 0.f, s1 = 0.f;
    for (int n = n0; n < nend; n++) {
        const int gn = g_batch[n];
        if (gn != g) {
            atomicAdd(&g_var[g * DIM + d0], s0);
            atomicAdd(&g_var[g * DIM + d1], s1);
            s0 = 0.f; s1 = 0.f; g = gn;
            ic = 1.f / fmaxf(g_cnt[g], 1.f);
            m0v = g_sum[g * DIM + d0] * ic * ms0;
            m1v = g_sum[g * DIM + d1] * ic * ms1;
        }
        const float* row = g_acc + (size_t)n * DIM;
        const float c0 = row[d0] - m0v;
        const float c1 = row[d1] - m1v;
        s0 += c0 * c0; s1 += c1 * c1;
    }
    atomicAdd(&g_var[g * DIM + d0], s0);
    atomicAdd(&g_var[g * DIM + d1], s1);
}

// ---------------------------------------------------------------- finalize: normalize + relu
__global__ __launch_bounds__(256) void k_final(const float* __restrict__ gw,
                                               const float* __restrict__ gb,
                                               const float* __restrict__ ms,
                                               float* __restrict__ out) {
    const int idx = blockIdx.x * blockDim.x + threadIdx.x;
    if (idx >= N_NODES * (DIM / 4)) return;
    const int n = idx >> 7;
    const int dc = (idx & 127) << 2;
    const int g = g_batch[n];
    const float ic = 1.f / fmaxf(g_cnt[g], 1.f);
    const float4 x  = *(const float4*)(g_acc + (size_t)n * DIM + dc);
    const float4 sm = *(const float4*)(g_sum + g * DIM + dc);
    const float4 vr = *(const float4*)(g_var + g * DIM + dc);
    const float4 w4 = *(const float4*)(gw + dc);
    const float4 b4 = *(const float4*)(gb + dc);
    const float4 m4 = *(const float4*)(ms + dc);
    float4 o;
    o.x = fmaxf(w4.x * (x.x - sm.x * ic * m4.x) * rsqrtf(vr.x * ic + EPSV) + b4.x, 0.f);
    o.y = fmaxf(w4.y * (x.y - sm.y * ic * m4.y) * rsqrtf(vr.y * ic + EPSV) + b4.y, 0.f);
    o.z = fmaxf(w4.z * (x.z - sm.z * ic * m4.z) * rsqrtf(vr.z * ic + EPSV) + b4.z, 0.f);
    o.w = fmaxf(w4.w * (x.w - sm.w * ic * m4.w) * rsqrtf(vr.w * ic + EPSV) + b4.w, 0.f);
    *(float4*)(out + (size_t)n * DIM + dc) = o;
}

// ---------------------------------------------------------------- launch
extern "C" void kernel_launch(void* const* d_in, const int* in_sizes, int n_in,
                              void* d_out, int out_size) {
    const float* node  = (const float*)d_in[0];
    const float* eattr = (const float*)d_in[1];
    const float* W     = (const float*)d_in[2];
    const float* b     = (const float*)d_in[3];
    const float* gw    = (const float*)d_in[4];
    const float* gb    = (const float*)d_in[5];
    const float* ms    = (const float*)d_in[6];
    const void*  ei    = d_in[7];
    const void*  batch = d_in[8];
    float* out = (float*)d_out;

    k_convert<<<(N_EDGES + 255) / 256, 256>>>(ei, batch);
    k_init<<<(N_NODES + 255) / 256, 256>>>();
    k_deg<<<(N_EDGES + 255) / 256, 256>>>(eattr);
    {
        dim3 grid(DIM / 128, (N_NODES + 127) / 128);
        k_gemm<<<grid, 256>>>(node, W, b);
    }
    k_scatter<<<N_EDGES, 128>>>(eattr);
    k_stats1<<<(N_NODES + 127) / 128, 256>>>();
    k_stats2<<<(N_NODES + 127) / 128, 256>>>(ms);
    k_final<<<(N_NODES * (DIM / 4) + 255) / 256, 256>>>(gw, gb, ms, out);
}

// round 4
// speedup vs baseline: 1.2135x; 1.2135x over previous
#include <cuda_runtime.h>
#include <cstdint>

#define N_NODES 50000
#define N_EDGES 160000
#define DIM     512
#define N_GRAPHS 64
#define EPSV    1e-5f

// GEMM tiling: BM=128, BN=256, BK=16, 8 warps, warp tile 64x64
#define AS_STR 20
#define BS_STR 264
#define AS_ELE (128 * AS_STR)          // 2560 floats / stage
#define BS_ELE (16 * BS_STR)           // 4224 floats / stage
#define SMEM_BYTES ((2 * AS_ELE + 2 * BS_ELE) * 4)   // 54272 B

// ---- scratch (static __device__: allocation-free) ----
__device__ float g_xw [(size_t)N_NODES * DIM];   // x @ W
__device__ float g_acc[(size_t)N_NODES * DIM];   // node + b + conv (accumulator)
__device__ float g_deg[N_NODES];
__device__ float g_sum[N_GRAPHS * DIM];
__device__ float g_sq [N_GRAPHS * DIM];
__device__ float g_cnt[N_GRAPHS];
__device__ int   g_ei_row[N_EDGES];
__device__ int   g_ei_col[N_EDGES];
__device__ int   g_batch [N_NODES];

// ---------------------------------------------------------------- dtype-robust index conversion
__global__ void k_convert(const void* __restrict__ ei, const void* __restrict__ batch) {
    __shared__ int s64;
    const int tid = threadIdx.x;
    if (tid == 0) {
        const long long* q = (const long long*)ei;
        int ok = 1;
#pragma unroll
        for (int i = 0; i < 8; i++) { long long v = q[i]; if (v < 0 || v >= N_NODES) ok = 0; }
        s64 = ok;
    }
    __syncthreads();
    const int is64 = s64;
    const int e = blockIdx.x * blockDim.x + tid;
    if (e < N_EDGES) {
        int r, c;
        if (is64) { r = (int)((const long long*)ei)[e]; c = (int)((const long long*)ei)[N_EDGES + e]; }
        else      { r = ((const int*)ei)[e];            c = ((const int*)ei)[N_EDGES + e]; }
        g_ei_row[e] = min(max(r, 0), N_NODES - 1);
        g_ei_col[e] = min(max(c, 0), N_NODES - 1);
    }
    if (e < N_NODES) {
        int bv = is64 ? (int)((const long long*)batch)[e] : ((const int*)batch)[e];
        g_batch[e] = min(max(bv, 0), N_GRAPHS - 1);
    }
}

// ---------------------------------------------------------------- init / degree
__global__ void k_init() {
    int i = blockIdx.x * blockDim.x + threadIdx.x;
    if (i < N_NODES) g_deg[i] = 1.0f;
    if (i < N_GRAPHS * DIM) { g_sum[i] = 0.f; g_sq[i] = 0.f; }
    if (i < N_GRAPHS) g_cnt[i] = 0.f;
}
__global__ void k_deg(const float* __restrict__ w) {
    int e = blockIdx.x * blockDim.x + threadIdx.x;
    if (e < N_EDGES) atomicAdd(&g_deg[g_ei_col[e]], w[e]);
}

// ---------------------------------------------------------------- tf32 helpers
__device__ __forceinline__ float tf32f(float x) {
    uint32_t r;
    asm("cvt.rna.tf32.f32 %0, %1;" : "=r"(r) : "f"(x));
    return __uint_as_float(r);
}
__device__ __forceinline__ void mma_tf32(float* d, const uint32_t* a, const uint32_t* b) {
    asm volatile(
        "mma.sync.aligned.m16n8k8.row.col.f32.tf32.tf32.f32 "
        "{%0,%1,%2,%3},{%4,%5,%6,%7},{%8,%9},{%0,%1,%2,%3};\n"
        : "+f"(d[0]), "+f"(d[1]), "+f"(d[2]), "+f"(d[3])
        : "r"(a[0]), "r"(a[1]), "r"(a[2]), "r"(a[3]), "r"(b[0]), "r"(b[1]));
}

// ---------------------------------------------------------------- GEMM + fused epilogue
// C = node @ W  (M=50000, N=512, K=512), tf32 mma.sync.
// BM=128 BN=256 BK=16, 8 warps (2x4), warp tile 64x64, mma grid 4x8.
// Epilogue: g_xw = C ; g_acc = node + b + C/deg.
__global__ void __launch_bounds__(256, 1) k_gemm(
    const float* __restrict__ A,      // node [M,512]
    const float* __restrict__ B,      // W [512,512]
    const float* __restrict__ bias)   // b [512]
{
    extern __shared__ float smem[];
    const int tid  = threadIdx.x;
    const int lane = tid & 31;
    const int warp = tid >> 5;
    const int wm = warp >> 2;   // 0..1  (64-row tile)
    const int wn = warp & 3;    // 0..3  (64-col tile)
    const int m0 = blockIdx.y * 128;
    const int n0 = blockIdx.x * 256;

    float acc[4][8][4];
#pragma unroll
    for (int i = 0; i < 4; i++)
#pragma unroll
        for (int j = 0; j < 8; j++)
#pragma unroll
            for (int c = 0; c < 4; c++) acc[i][j][c] = 0.f;

    float4 av[2], bv[4];

#define LOAD_TILES(KT) do {                                                      \
        const int kk = (KT) * 16;                                                \
        _Pragma("unroll")                                                        \
        for (int i = 0; i < 2; i++) {                                            \
            const int idx = tid + i * 256;                                       \
            int gm = m0 + (idx >> 2);                                            \
            if (gm >= N_NODES) gm = N_NODES - 1;                                 \
            av[i] = *(const float4*)(A + (size_t)gm * 512 + kk + (idx & 3) * 4); \
        }                                                                        \
        _Pragma("unroll")                                                        \
        for (int i = 0; i < 4; i++) {                                            \
            const int idx = tid + i * 256;                                       \
            bv[i] = *(const float4*)(B + (size_t)(kk + (idx >> 6)) * 512         \
                                       + n0 + (idx & 63) * 4);                   \
        }                                                                        \
    } while (0)

#define STORE_TILES(BUF) do {                                                    \
        float* as_ = smem + (BUF) * AS_ELE;                                      \
        float* bs_ = smem + 2 * AS_ELE + (BUF) * BS_ELE;                         \
        _Pragma("unroll")                                                        \
        for (int i = 0; i < 2; i++) {                                            \
            const int idx = tid + i * 256;                                       \
            float* p = as_ + (idx >> 2) * AS_STR + (idx & 3) * 4;                \
            p[0]=tf32f(av[i].x); p[1]=tf32f(av[i].y);                            \
            p[2]=tf32f(av[i].z); p[3]=tf32f(av[i].w);                            \
        }                                                                        \
        _Pragma("unroll")                                                        \
        for (int i = 0; i < 4; i++) {                                            \
            const int idx = tid + i * 256;                                       \
            float* p = bs_ + (idx >> 6) * BS_STR + (idx & 63) * 4;               \
            p[0]=tf32f(bv[i].x); p[1]=tf32f(bv[i].y);                            \
            p[2]=tf32f(bv[i].z); p[3]=tf32f(bv[i].w);                            \
        }                                                                        \
    } while (0)

    LOAD_TILES(0);
    STORE_TILES(0);
    __syncthreads();

#pragma unroll 1
    for (int kt = 0; kt < 32; kt++) {
        const int buf = kt & 1;
        if (kt < 31) LOAD_TILES(kt + 1);
        const float* as = smem + buf * AS_ELE;
        const float* bs = smem + 2 * AS_ELE + buf * BS_ELE;
#pragma unroll
        for (int ks = 0; ks < 2; ks++) {
            uint32_t af[4][4], bf[8][2];
            const int kk = ks * 8 + (lane & 3);
#pragma unroll
            for (int i = 0; i < 4; i++) {
                const int r = wm * 64 + i * 16 + (lane >> 2);
                af[i][0] = __float_as_uint(as[r * AS_STR + kk]);
                af[i][1] = __float_as_uint(as[(r + 8) * AS_STR + kk]);
                af[i][2] = __float_as_uint(as[r * AS_STR + kk + 4]);
                af[i][3] = __float_as_uint(as[(r + 8) * AS_STR + kk + 4]);
            }
#pragma unroll
            for (int j = 0; j < 8; j++) {
                const int c = wn * 64 + j * 8 + (lane >> 2);
                bf[j][0] = __float_as_uint(bs[kk * BS_STR + c]);
                bf[j][1] = __float_as_uint(bs[(kk + 4) * BS_STR + c]);
            }
#pragma unroll
            for (int i = 0; i < 4; i++)
#pragma unroll
                for (int j = 0; j < 8; j++)
                    mma_tf32(acc[i][j], af[i], bf[j]);
        }
        if (kt < 31) STORE_TILES(buf ^ 1);
        __syncthreads();
    }

    // epilogue: xw -> g_xw ; g_acc = node + b + xw/deg
#pragma unroll
    for (int i = 0; i < 4; i++) {
        const int rbase = m0 + wm * 64 + i * 16 + (lane >> 2);
#pragma unroll
        for (int h = 0; h < 2; h++) {
            const int gm = rbase + h * 8;
            if (gm < N_NODES) {
                const float invdeg = 1.0f / g_deg[gm];
#pragma unroll
                for (int j = 0; j < 8; j++) {
                    const int cb = n0 + wn * 64 + j * 8 + ((lane & 3) << 1);
                    const size_t o = (size_t)gm * 512 + cb;
                    const float v0 = acc[i][j][h * 2 + 0];
                    const float v1 = acc[i][j][h * 2 + 1];
                    *(float2*)(g_xw + o) = make_float2(v0, v1);
                    const float2 a2 = *(const float2*)(A + o);
                    const float2 b2 = *(const float2*)(bias + cb);
                    *(float2*)(g_acc + o) = make_float2(a2.x + b2.x + v0 * invdeg,
                                                        a2.y + b2.y + v1 * invdeg);
                }
            }
        }
    }
#undef LOAD_TILES
#undef STORE_TILES
}

// ---------------------------------------------------------------- edge scatter
__global__ __launch_bounds__(128) void k_scatter(const float* __restrict__ w) {
    const int e = blockIdx.x;
    const int r = g_ei_row[e];
    const int c = g_ei_col[e];
    const float coef = w[e] * rsqrtf(g_deg[r]) * rsqrtf(g_deg[c]);
    const float4* src = (const float4*)(g_xw + (size_t)r * DIM);
    float4* dst = (float4*)(g_acc + (size_t)c * DIM);
    const int t = threadIdx.x;
    float4 v = src[t];
    asm volatile("red.global.add.v4.f32 [%0], {%1,%2,%3,%4};"
                 :: "l"(dst + t), "f"(v.x * coef), "f"(v.y * coef),
                    "f"(v.z * coef), "f"(v.w * coef)
                 : "memory");
}

// ---------------------------------------------------------------- GraphNorm stats: sum + sumsq + count (single pass)
__global__ __launch_bounds__(256) void k_stats() {
    const int n0 = blockIdx.x * 128;
    const int nend = min(n0 + 128, N_NODES);
    const int t = threadIdx.x;
    const int d0 = t, d1 = t + 256;
    float s0 = 0.f, s1 = 0.f, q0 = 0.f, q1 = 0.f;
    int g = g_batch[n0], cnt = 0;
    for (int n = n0; n < nend; n++) {
        const int gn = g_batch[n];
        if (gn != g) {
            atomicAdd(&g_sum[g * DIM + d0], s0);
            atomicAdd(&g_sum[g * DIM + d1], s1);
            atomicAdd(&g_sq [g * DIM + d0], q0);
            atomicAdd(&g_sq [g * DIM + d1], q1);
            if (t == 0) atomicAdd(&g_cnt[g], (float)cnt);
            s0 = s1 = q0 = q1 = 0.f; cnt = 0; g = gn;
        }
        const float* row = g_acc + (size_t)n * DIM;
        const float x0 = row[d0], x1 = row[d1];
        s0 += x0; s1 += x1; q0 += x0 * x0; q1 += x1 * x1; cnt++;
    }
    atomicAdd(&g_sum[g * DIM + d0], s0);
    atomicAdd(&g_sum[g * DIM + d1], s1);
    atomicAdd(&g_sq [g * DIM + d0], q0);
    atomicAdd(&g_sq [g * DIM + d1], q1);
    if (t == 0) atomicAdd(&g_cnt[g], (float)cnt);
}

// ---------------------------------------------------------------- finalize: normalize + relu
// var = E[x^2] - 2*c*m + c^2, c = m*mean_scale, m = E[x]
__global__ __launch_bounds__(256) void k_final(const float* __restrict__ gw,
                                               const float* __restrict__ gb,
                                               const float* __restrict__ ms,
                                               float* __restrict__ out) {
    const int idx = blockIdx.x * blockDim.x + threadIdx.x;
    if (idx >= N_NODES * (DIM / 4)) return;
    const int n = idx >> 7;
    const int dc = (idx & 127) << 2;
    const int g = g_batch[n];
    const float ic = 1.f / fmaxf(g_cnt[g], 1.f);
    const float4 x  = *(const float4*)(g_acc + (size_t)n * DIM + dc);
    const float4 sm = *(const float4*)(g_sum + g * DIM + dc);
    const float4 sq = *(const float4*)(g_sq  + g * DIM + dc);
    const float4 w4 = *(const float4*)(gw + dc);
    const float4 b4 = *(const float4*)(gb + dc);
    const float4 m4 = *(const float4*)(ms + dc);
    float4 o;
    {
        const float m = sm.x * ic, c = m * m4.x;
        const float var = sq.x * ic - 2.f * c * m + c * c;
        o.x = fmaxf(w4.x * (x.x - c) * rsqrtf(var + EPSV) + b4.x, 0.f);
    }
    {
        const float m = sm.y * ic, c = m * m4.y;
        const float var = sq.y * ic - 2.f * c * m + c * c;
        o.y = fmaxf(w4.y * (x.y - c) * rsqrtf(var + EPSV) + b4.y, 0.f);
    }
    {
        const float m = sm.z * ic, c = m * m4.z;
        const float var = sq.z * ic - 2.f * c * m + c * c;
        o.z = fmaxf(w4.z * (x.z - c) * rsqrtf(var + EPSV) + b4.z, 0.f);
    }
    {
        const float m = sm.w * ic, c = m * m4.w;
        const float var = sq.w * ic - 2.f * c * m + c * c;
        o.w = fmaxf(w4.w * (x.w - c) * rsqrtf(var + EPSV) + b4.w, 0.f);
    }
    *(float4*)(out + (size_t)n * DIM + dc) = o;
}

// ---------------------------------------------------------------- launch
extern "C" void kernel_launch(void* const* d_in, const int* in_sizes, int n_in,
                              void* d_out, int out_size) {
    const float* node  = (const float*)d_in[0];
    const float* eattr = (const float*)d_in[1];
    const float* W     = (const float*)d_in[2];
    const float* b     = (const float*)d_in[3];
    const float* gw    = (const float*)d_in[4];
    const float* gb    = (const float*)d_in[5];
    const float* ms    = (const float*)d_in[6];
    const void*  ei    = d_in[7];
    const void*  batch = d_in[8];
    float* out = (float*)d_out;

    cudaFuncSetAttribute(k_gemm, cudaFuncAttributeMaxDynamicSharedMemorySize, SMEM_BYTES);

    k_convert<<<(N_EDGES + 255) / 256, 256>>>(ei, batch);
    k_init<<<(N_NODES + 255) / 256, 256>>>();
    k_deg<<<(N_EDGES + 255) / 256, 256>>>(eattr);
    {
        dim3 grid(DIM / 256, (N_NODES + 127) / 128);   // (2, 391)
        k_gemm<<<grid, 256, SMEM_BYTES>>>(node, W, b);
    }
    k_scatter<<<N_EDGES, 128>>>(eattr);
    k_stats<<<(N_NODES + 127) / 128, 256>>>();
    k_final<<<(N_NODES * (DIM / 4) + 255) / 256, 256>>>(gw, gb, ms, out);
}

// round 5
// speedup vs baseline: 1.2232x; 1.0079x over previous
#include <cuda_runtime.h>
#include <cstdint>

#define N_NODES 50000
#define N_EDGES 160000
#define DIM     512
#define N_GRAPHS 64
#define EPSV    1e-5f

// GEMM tiling: BM=128, BN=256, BK=32, 3-stage cp.async, 8 warps, warp tile 64x64
#define AS_STR 36                      // floats per A row (32 + 4 pad, 16B-aligned)
#define BS_STR 264                     // floats per B row (256 + 8 pad)
#define AS_ELE (128 * AS_STR)          // 4608 floats / stage
#define BS_ELE (32 * BS_STR)           // 8448 floats / stage
#define NSTAGE 3
#define SMEM_BYTES (NSTAGE * (AS_ELE + BS_ELE) * 4)   // 156672 B

// ---- scratch (static __device__: allocation-free) ----
__device__ float g_xw [(size_t)N_NODES * DIM];   // x @ W
__device__ float g_acc[(size_t)N_NODES * DIM];   // node + b + conv (accumulator)
__device__ float g_deg[N_NODES];
__device__ float g_sum[N_GRAPHS * DIM];
__device__ float g_sq [N_GRAPHS * DIM];
__device__ float g_cnt[N_GRAPHS];
__device__ int   g_ei_row[N_EDGES];
__device__ int   g_ei_col[N_EDGES];
__device__ int   g_batch [N_NODES];

// ---------------------------------------------------------------- dtype-robust index conversion
__global__ void k_convert(const void* __restrict__ ei, const void* __restrict__ batch) {
    __shared__ int s64;
    const int tid = threadIdx.x;
    if (tid == 0) {
        const long long* q = (const long long*)ei;
        int ok = 1;
#pragma unroll
        for (int i = 0; i < 8; i++) { long long v = q[i]; if (v < 0 || v >= N_NODES) ok = 0; }
        s64 = ok;
    }
    __syncthreads();
    const int is64 = s64;
    const int e = blockIdx.x * blockDim.x + tid;
    if (e < N_EDGES) {
        int r, c;
        if (is64) { r = (int)((const long long*)ei)[e]; c = (int)((const long long*)ei)[N_EDGES + e]; }
        else      { r = ((const int*)ei)[e];            c = ((const int*)ei)[N_EDGES + e]; }
        g_ei_row[e] = min(max(r, 0), N_NODES - 1);
        g_ei_col[e] = min(max(c, 0), N_NODES - 1);
    }
    if (e < N_NODES) {
        int bv = is64 ? (int)((const long long*)batch)[e] : ((const int*)batch)[e];
        g_batch[e] = min(max(bv, 0), N_GRAPHS - 1);
    }
}

// ---------------------------------------------------------------- init / degree
__global__ void k_init() {
    int i = blockIdx.x * blockDim.x + threadIdx.x;
    if (i < N_NODES) g_deg[i] = 1.0f;
    if (i < N_GRAPHS * DIM) { g_sum[i] = 0.f; g_sq[i] = 0.f; }
    if (i < N_GRAPHS) g_cnt[i] = 0.f;
}
__global__ void k_deg(const float* __restrict__ w) {
    int e = blockIdx.x * blockDim.x + threadIdx.x;
    if (e < N_EDGES) atomicAdd(&g_deg[g_ei_col[e]], w[e]);
}

// ---------------------------------------------------------------- helpers
__device__ __forceinline__ uint32_t smem_u32(const void* p) {
    uint32_t a;
    asm("{ .reg .u64 t; cvta.to.shared.u64 t, %1; cvt.u32.u64 %0, t; }" : "=r"(a) : "l"(p));
    return a;
}
__device__ __forceinline__ void cpasync16(uint32_t dst, const void* src) {
    asm volatile("cp.async.cg.shared.global [%0], [%1], 16;" :: "r"(dst), "l"(src));
}
#define CP_COMMIT()  asm volatile("cp.async.commit_group;" ::: "memory")
#define CP_WAIT(n)   asm volatile("cp.async.wait_group %0;" :: "n"(n) : "memory")

__device__ __forceinline__ void mma_tf32(float* d, const uint32_t* a, const uint32_t* b) {
    asm volatile(
        "mma.sync.aligned.m16n8k8.row.col.f32.tf32.tf32.f32 "
        "{%0,%1,%2,%3},{%4,%5,%6,%7},{%8,%9},{%0,%1,%2,%3};\n"
        : "+f"(d[0]), "+f"(d[1]), "+f"(d[2]), "+f"(d[3])
        : "r"(a[0]), "r"(a[1]), "r"(a[2]), "r"(a[3]), "r"(b[0]), "r"(b[1]));
}

// ---------------------------------------------------------------- GEMM + fused epilogue
// C = node @ W  (M=50000, N=512, K=512), tf32 mma.sync (f32 bits truncated by HW).
// BM=128 BN=256 BK=32, 3-stage cp.async pipeline, warp tile 64x64, mma grid 4x8.
// Epilogue: g_xw = C ; g_acc = node + b + C/deg.
__global__ void __launch_bounds__(256, 1) k_gemm(
    const float* __restrict__ A,      // node [M,512]
    const float* __restrict__ B,      // W [512,512]
    const float* __restrict__ bias)   // b [512]
{
    extern __shared__ float smem[];
    const uint32_t sbase = smem_u32(smem);
    const int tid  = threadIdx.x;
    const int lane = tid & 31;
    const int warp = tid >> 5;
    const int wm = warp >> 2;   // 0..1  (64-row tile)
    const int wn = warp & 3;    // 0..3  (64-col tile)
    const int m0 = blockIdx.y * 128;
    const int n0 = blockIdx.x * 256;

    float acc[4][8][4];
#pragma unroll
    for (int i = 0; i < 4; i++)
#pragma unroll
        for (int j = 0; j < 8; j++)
#pragma unroll
            for (int c = 0; c < 4; c++) acc[i][j][c] = 0.f;

    // issue one k-stage of cp.async (A: 1024 x 16B, B: 2048 x 16B)
#define ISSUE(KT) do {                                                           \
        const int kk = (KT) * 32;                                                \
        const uint32_t sa = sbase + ((KT) % NSTAGE) * (AS_ELE * 4);              \
        const uint32_t sbb = sbase + (NSTAGE * AS_ELE + ((KT) % NSTAGE) * BS_ELE) * 4; \
        _Pragma("unroll")                                                        \
        for (int i = 0; i < 4; i++) {                                            \
            const int idx = tid + i * 256;                                       \
            const int row = idx >> 3, col = (idx & 7) * 4;                       \
            int gm = m0 + row;                                                   \
            if (gm >= N_NODES) gm = N_NODES - 1;                                 \
            cpasync16(sa + (uint32_t)(row * AS_STR + col) * 4,                   \
                      A + (size_t)gm * 512 + kk + col);                          \
        }                                                                        \
        _Pragma("unroll")                                                        \
        for (int i = 0; i < 8; i++) {                                            \
            const int idx = tid + i * 256;                                       \
            const int row = idx >> 6, col = (idx & 63) * 4;                      \
            cpasync16(sbb + (uint32_t)(row * BS_STR + col) * 4,                  \
                      B + (size_t)(kk + row) * 512 + n0 + col);                  \
        }                                                                        \
        CP_COMMIT();                                                             \
    } while (0)

    ISSUE(0);
    ISSUE(1);

#pragma unroll 1
    for (int kt = 0; kt < 16; kt++) {
        CP_WAIT(1);          // stage kt resident
        __syncthreads();     // visible to all warps; all done with stage (kt-1)%3
        if (kt + 2 < 16) ISSUE(kt + 2);   // fills stage (kt+2)%3 == (kt-1)%3: safe

        const float* as = smem + (kt % NSTAGE) * AS_ELE;
        const float* bs = smem + NSTAGE * AS_ELE + (kt % NSTAGE) * BS_ELE;
#pragma unroll
        for (int ks = 0; ks < 4; ks++) {
            uint32_t af[4][4], bf[8][2];
            const int kk = ks * 8 + (lane & 3);
#pragma unroll
            for (int i = 0; i < 4; i++) {
                const int r = wm * 64 + i * 16 + (lane >> 2);
                af[i][0] = __float_as_uint(as[r * AS_STR + kk]);
                af[i][1] = __float_as_uint(as[(r + 8) * AS_STR + kk]);
                af[i][2] = __float_as_uint(as[r * AS_STR + kk + 4]);
                af[i][3] = __float_as_uint(as[(r + 8) * AS_STR + kk + 4]);
            }
#pragma unroll
            for (int j = 0; j < 8; j++) {
                const int c = wn * 64 + j * 8 + (lane >> 2);
                bf[j][0] = __float_as_uint(bs[kk * BS_STR + c]);
                bf[j][1] = __float_as_uint(bs[(kk + 4) * BS_STR + c]);
            }
#pragma unroll
            for (int i = 0; i < 4; i++)
#pragma unroll
                for (int j = 0; j < 8; j++)
                    mma_tf32(acc[i][j], af[i], bf[j]);
        }
    }

    // epilogue: xw -> g_xw ; g_acc = node + b + xw/deg
#pragma unroll
    for (int i = 0; i < 4; i++) {
        const int rbase = m0 + wm * 64 + i * 16 + (lane >> 2);
#pragma unroll
        for (int h = 0; h < 2; h++) {
            const int gm = rbase + h * 8;
            if (gm < N_NODES) {
                const float invdeg = 1.0f / g_deg[gm];
#pragma unroll
                for (int j = 0; j < 8; j++) {
                    const int cb = n0 + wn * 64 + j * 8 + ((lane & 3) << 1);
                    const size_t o = (size_t)gm * 512 + cb;
                    const float v0 = acc[i][j][h * 2 + 0];
                    const float v1 = acc[i][j][h * 2 + 1];
                    *(float2*)(g_xw + o) = make_float2(v0, v1);
                    const float2 a2 = *(const float2*)(A + o);
                    const float2 b2 = *(const float2*)(bias + cb);
                    *(float2*)(g_acc + o) = make_float2(a2.x + b2.x + v0 * invdeg,
                                                        a2.y + b2.y + v1 * invdeg);
                }
            }
        }
    }
#undef ISSUE
}

// ---------------------------------------------------------------- edge scatter
__global__ __launch_bounds__(128) void k_scatter(const float* __restrict__ w) {
    const int e = blockIdx.x;
    const int r = g_ei_row[e];
    const int c = g_ei_col[e];
    const float coef = w[e] * rsqrtf(g_deg[r]) * rsqrtf(g_deg[c]);
    const float4* src = (const float4*)(g_xw + (size_t)r * DIM);
    float4* dst = (float4*)(g_acc + (size_t)c * DIM);
    const int t = threadIdx.x;
    float4 v = src[t];
    asm volatile("red.global.add.v4.f32 [%0], {%1,%2,%3,%4};"
                 :: "l"(dst + t), "f"(v.x * coef), "f"(v.y * coef),
                    "f"(v.z * coef), "f"(v.w * coef)
                 : "memory");
}

// ---------------------------------------------------------------- GraphNorm stats (single pass)
__global__ __launch_bounds__(256) void k_stats() {
    const int n0 = blockIdx.x * 128;
    const int nend = min(n0 + 128, N_NODES);
    const int t = threadIdx.x;
    const int d0 = t, d1 = t + 256;
    float s0 = 0.f, s1 = 0.f, q0 = 0.f, q1 = 0.f;
    int g = g_batch[n0], cnt = 0;
    for (int n = n0; n < nend; n++) {
        const int gn = g_batch[n];
        if (gn != g) {
            atomicAdd(&g_sum[g * DIM + d0], s0);
            atomicAdd(&g_sum[g * DIM + d1], s1);
            atomicAdd(&g_sq [g * DIM + d0], q0);
            atomicAdd(&g_sq [g * DIM + d1], q1);
            if (t == 0) atomicAdd(&g_cnt[g], (float)cnt);
            s0 = s1 = q0 = q1 = 0.f; cnt = 0; g = gn;
        }
        const float* row = g_acc + (size_t)n * DIM;
        const float x0 = row[d0], x1 = row[d1];
        s0 += x0; s1 += x1; q0 += x0 * x0; q1 += x1 * x1; cnt++;
    }
    atomicAdd(&g_sum[g * DIM + d0], s0);
    atomicAdd(&g_sum[g * DIM + d1], s1);
    atomicAdd(&g_sq [g * DIM + d0], q0);
    atomicAdd(&g_sq [g * DIM + d1], q1);
    if (t == 0) atomicAdd(&g_cnt[g], (float)cnt);
}

// ---------------------------------------------------------------- finalize: normalize + relu
__global__ __launch_bounds__(256) void k_final(const float* __restrict__ gw,
                                               const float* __restrict__ gb,
                                               const float* __restrict__ ms,
                                               float* __restrict__ out) {
    const int idx = blockIdx.x * blockDim.x + threadIdx.x;
    if (idx >= N_NODES * (DIM / 4)) return;
    const int n = idx >> 7;
    const int dc = (idx & 127) << 2;
    const int g = g_batch[n];
    const float ic = 1.f / fmaxf(g_cnt[g], 1.f);
    const float4 x  = *(const float4*)(g_acc + (size_t)n * DIM + dc);
    const float4 sm = *(const float4*)(g_sum + g * DIM + dc);
    const float4 sq = *(const float4*)(g_sq  + g * DIM + dc);
    const float4 w4 = *(const float4*)(gw + dc);
    const float4 b4 = *(const float4*)(gb + dc);
    const float4 m4 = *(const float4*)(ms + dc);
    float4 o;
    {
        const float m = sm.x * ic, c = m * m4.x;
        const float var = sq.x * ic - 2.f * c * m + c * c;
        o.x = fmaxf(w4.x * (x.x - c) * rsqrtf(var + EPSV) + b4.x, 0.f);
    }
    {
        const float m = sm.y * ic, c = m * m4.y;
        const float var = sq.y * ic - 2.f * c * m + c * c;
        o.y = fmaxf(w4.y * (x.y - c) * rsqrtf(var + EPSV) + b4.y, 0.f);
    }
    {
        const float m = sm.z * ic, c = m * m4.z;
        const float var = sq.z * ic - 2.f * c * m + c * c;
        o.z = fmaxf(w4.z * (x.z - c) * rsqrtf(var + EPSV) + b4.z, 0.f);
    }
    {
        const float m = sm.w * ic, c = m * m4.w;
        const float var = sq.w * ic - 2.f * c * m + c * c;
        o.w = fmaxf(w4.w * (x.w - c) * rsqrtf(var + EPSV) + b4.w, 0.f);
    }
    *(float4*)(out + (size_t)n * DIM + dc) = o;
}

// ---------------------------------------------------------------- launch
extern "C" void kernel_launch(void* const* d_in, const int* in_sizes, int n_in,
                              void* d_out, int out_size) {
    const float* node  = (const float*)d_in[0];
    const float* eattr = (const float*)d_in[1];
    const float* W     = (const float*)d_in[2];
    const float* b     = (const float*)d_in[3];
    const float* gw    = (const float*)d_in[4];
    const float* gb    = (const float*)d_in[5];
    const float* ms    = (const float*)d_in[6];
    const void*  ei    = d_in[7];
    const void*  batch = d_in[8];
    float* out = (float*)d_out;

    cudaFuncSetAttribute(k_gemm, cudaFuncAttributeMaxDynamicSharedMemorySize, SMEM_BYTES);

    k_convert<<<(N_EDGES + 255) / 256, 256>>>(ei, batch);
    k_init<<<(N_NODES + 255) / 256, 256>>>();
    k_deg<<<(N_EDGES + 255) / 256, 256>>>(eattr);
    {
        dim3 grid(DIM / 256, (N_NODES + 127) / 128);   // (2, 391)
        k_gemm<<<grid, 256, SMEM_BYTES>>>(node, W, b);
    }
    k_scatter<<<N_EDGES, 128>>>(eattr);
    k_stats<<<(N_NODES + 127) / 128, 256>>>();
    k_final<<<(N_NODES * (DIM / 4) + 255) / 256, 256>>>(gw, gb, ms, out);
}

// round 6
// speedup vs baseline: 1.2869x; 1.0521x over previous
#include <cuda_runtime.h>
#include <cstdint>

#define N_NODES 50000
#define N_EDGES 160000
#define DIM     512
#define N_GRAPHS 64
#define EPSV    1e-5f

// GEMM tiling: BM=128, BN=256, BK=32, 3-stage cp.async, 16 warps, warp tile 64x32
#define AS_STR 36                      // floats per A row (32 + 4 pad)
#define BS_STR 264                     // floats per B row (256 + 8 pad)
#define AS_ELE (128 * AS_STR)
#define BS_ELE (32 * BS_STR)
#define NSTAGE 3
#define SMEM_BYTES (NSTAGE * (AS_ELE + BS_ELE) * 4)   // 156672 B

// ---- scratch (static __device__: allocation-free) ----
__device__ float g_xw [(size_t)N_NODES * DIM];
__device__ float g_acc[(size_t)N_NODES * DIM];
__device__ float g_deg[N_NODES];
__device__ float g_sum[N_GRAPHS * DIM];
__device__ float g_sq [N_GRAPHS * DIM];
__device__ float g_cnt[N_GRAPHS];
__device__ int   g_ei_row[N_EDGES];
__device__ int   g_ei_col[N_EDGES];
__device__ int   g_batch [N_NODES];

// ---------------------------------------------------------------- init
__global__ void k_init() {
    int i = blockIdx.x * blockDim.x + threadIdx.x;
    if (i < N_NODES) g_deg[i] = 1.0f;               // self-loop weight
    if (i < N_GRAPHS * DIM) { g_sum[i] = 0.f; g_sq[i] = 0.f; }
    if (i < N_GRAPHS) g_cnt[i] = 0.f;
}

// ---------------------------------------------------------------- dtype-robust index conversion + degree
__global__ void k_convert(const void* __restrict__ ei, const void* __restrict__ batch,
                          const float* __restrict__ w) {
    __shared__ int s64;
    const int tid = threadIdx.x;
    if (tid == 0) {
        const long long* q = (const long long*)ei;
        int ok = 1;
#pragma unroll
        for (int i = 0; i < 8; i++) { long long v = q[i]; if (v < 0 || v >= N_NODES) ok = 0; }
        s64 = ok;
    }
    __syncthreads();
    const int is64 = s64;
    const int e = blockIdx.x * blockDim.x + tid;
    if (e < N_EDGES) {
        int r, c;
        if (is64) { r = (int)((const long long*)ei)[e]; c = (int)((const long long*)ei)[N_EDGES + e]; }
        else      { r = ((const int*)ei)[e];            c = ((const int*)ei)[N_EDGES + e]; }
        r = min(max(r, 0), N_NODES - 1);
        c = min(max(c, 0), N_NODES - 1);
        g_ei_row[e] = r;
        g_ei_col[e] = c;
        atomicAdd(&g_deg[c], w[e]);     // weighted in-degree (g_deg pre-init to 1)
    }
    if (e < N_NODES) {
        int bv = is64 ? (int)((const long long*)batch)[e] : ((const int*)batch)[e];
        g_batch[e] = min(max(bv, 0), N_GRAPHS - 1);
    }
}

// ---------------------------------------------------------------- helpers
__device__ __forceinline__ void cpasync16(uint32_t dst, const void* src) {
    asm volatile("cp.async.cg.shared.global [%0], [%1], 16;" :: "r"(dst), "l"(src));
}
#define CP_COMMIT()  asm volatile("cp.async.commit_group;" ::: "memory")
#define CP_WAIT(n)   asm volatile("cp.async.wait_group %0;" :: "n"(n) : "memory")
__device__ __forceinline__ uint32_t smem_u32(const void* p) {
    uint32_t a;
    asm("{ .reg .u64 t; cvta.to.shared.u64 t, %1; cvt.u32.u64 %0, t; }" : "=r"(a) : "l"(p));
    return a;
}
__device__ __forceinline__ void mma_tf32(float* d, const uint32_t* a, const uint32_t* b) {
    asm volatile(
        "mma.sync.aligned.m16n8k8.row.col.f32.tf32.tf32.f32 "
        "{%0,%1,%2,%3},{%4,%5,%6,%7},{%8,%9},{%0,%1,%2,%3};\n"
        : "+f"(d[0]), "+f"(d[1]), "+f"(d[2]), "+f"(d[3])
        : "r"(a[0]), "r"(a[1]), "r"(a[2]), "r"(a[3]), "r"(b[0]), "r"(b[1]));
}

// ---------------------------------------------------------------- GEMM + fused epilogue
// C = node @ W, tf32 mma.sync.  512 threads / 16 warps (2x8), warp tile 64x32.
// 3-stage cp.async, BK=32.  Epilogue: g_xw = C ; g_acc = node + b + C/deg.
__global__ void __launch_bounds__(512, 1) k_gemm(
    const float* __restrict__ A,
    const float* __restrict__ B,
    const float* __restrict__ bias)
{
    extern __shared__ float smem[];
    const uint32_t sbase = smem_u32(smem);
    const int tid  = threadIdx.x;
    const int lane = tid & 31;
    const int warp = tid >> 5;
    const int wm = warp >> 3;   // 0..1  (64-row tile)
    const int wn = warp & 7;    // 0..7  (32-col tile)
    const int m0 = blockIdx.y * 128;
    const int n0 = blockIdx.x * 256;

    float acc[4][4][4];
#pragma unroll
    for (int i = 0; i < 4; i++)
#pragma unroll
        for (int j = 0; j < 4; j++)
#pragma unroll
            for (int c = 0; c < 4; c++) acc[i][j][c] = 0.f;

#define ISSUE(KT) do {                                                           \
        const int kk = (KT) * 32;                                                \
        const uint32_t sa = sbase + ((KT) % NSTAGE) * (AS_ELE * 4);              \
        const uint32_t sbb = sbase + (NSTAGE * AS_ELE + ((KT) % NSTAGE) * BS_ELE) * 4; \
        _Pragma("unroll")                                                        \
        for (int i = 0; i < 2; i++) {                                            \
            const int idx = tid + i * 512;                                       \
            const int row = idx >> 3, col = (idx & 7) * 4;                       \
            int gm = m0 + row;                                                   \
            if (gm >= N_NODES) gm = N_NODES - 1;                                 \
            cpasync16(sa + (uint32_t)(row * AS_STR + col) * 4,                   \
                      A + (size_t)gm * 512 + kk + col);                          \
        }                                                                        \
        _Pragma("unroll")                                                        \
        for (int i = 0; i < 4; i++) {                                            \
            const int idx = tid + i * 512;                                       \
            const int row = idx >> 6, col = (idx & 63) * 4;                      \
            cpasync16(sbb + (uint32_t)(row * BS_STR + col) * 4,                  \
                      B + (size_t)(kk + row) * 512 + n0 + col);                  \
        }                                                                        \
        CP_COMMIT();                                                             \
    } while (0)

    ISSUE(0);
    ISSUE(1);

#pragma unroll 1
    for (int kt = 0; kt < 16; kt++) {
        CP_WAIT(1);
        __syncthreads();
        if (kt + 2 < 16) ISSUE(kt + 2);

        const float* as = smem + (kt % NSTAGE) * AS_ELE;
        const float* bs = smem + NSTAGE * AS_ELE + (kt % NSTAGE) * BS_ELE;
#pragma unroll
        for (int ks = 0; ks < 4; ks++) {
            uint32_t af[4][4], bf[4][2];
            const int kk = ks * 8 + (lane & 3);
#pragma unroll
            for (int i = 0; i < 4; i++) {
                const int r = wm * 64 + i * 16 + (lane >> 2);
                af[i][0] = __float_as_uint(as[r * AS_STR + kk]);
                af[i][1] = __float_as_uint(as[(r + 8) * AS_STR + kk]);
                af[i][2] = __float_as_uint(as[r * AS_STR + kk + 4]);
                af[i][3] = __float_as_uint(as[(r + 8) * AS_STR + kk + 4]);
            }
#pragma unroll
            for (int j = 0; j < 4; j++) {
                const int c = wn * 32 + j * 8 + (lane >> 2);
                bf[j][0] = __float_as_uint(bs[kk * BS_STR + c]);
                bf[j][1] = __float_as_uint(bs[(kk + 4) * BS_STR + c]);
            }
#pragma unroll
            for (int i = 0; i < 4; i++)
#pragma unroll
                for (int j = 0; j < 4; j++)
                    mma_tf32(acc[i][j], af[i], bf[j]);
        }
    }

    // epilogue
#pragma unroll
    for (int i = 0; i < 4; i++) {
        const int rbase = m0 + wm * 64 + i * 16 + (lane >> 2);
#pragma unroll
        for (int h = 0; h < 2; h++) {
            const int gm = rbase + h * 8;
            if (gm < N_NODES) {
                const float invdeg = 1.0f / g_deg[gm];
#pragma unroll
                for (int j = 0; j < 4; j++) {
                    const int cb = n0 + wn * 32 + j * 8 + ((lane & 3) << 1);
                    const size_t o = (size_t)gm * 512 + cb;
                    const float v0 = acc[i][j][h * 2 + 0];
                    const float v1 = acc[i][j][h * 2 + 1];
                    *(float2*)(g_xw + o) = make_float2(v0, v1);
                    const float2 a2 = *(const float2*)(A + o);
                    const float2 b2 = *(const float2*)(bias + cb);
                    *(float2*)(g_acc + o) = make_float2(a2.x + b2.x + v0 * invdeg,
                                                        a2.y + b2.y + v1 * invdeg);
                }
            }
        }
    }
#undef ISSUE
}

// ---------------------------------------------------------------- edge scatter
__global__ __launch_bounds__(128) void k_scatter(const float* __restrict__ w) {
    const int e = blockIdx.x;
    const int r = g_ei_row[e];
    const int c = g_ei_col[e];
    const float coef = w[e] * rsqrtf(g_deg[r]) * rsqrtf(g_deg[c]);
    const float4* src = (const float4*)(g_xw + (size_t)r * DIM);
    float4* dst = (float4*)(g_acc + (size_t)c * DIM);
    const int t = threadIdx.x;
    float4 v = src[t];
    asm volatile("red.global.add.v4.f32 [%0], {%1,%2,%3,%4};"
                 :: "l"(dst + t), "f"(v.x * coef), "f"(v.y * coef),
                    "f"(v.z * coef), "f"(v.w * coef)
                 : "memory");
}

// ---------------------------------------------------------------- GraphNorm stats (single pass)
__global__ __launch_bounds__(256) void k_stats() {
    const int n0 = blockIdx.x * 128;
    const int nend = min(n0 + 128, N_NODES);
    const int t = threadIdx.x;
    const int d0 = t, d1 = t + 256;
    float s0 = 0.f, s1 = 0.f, q0 = 0.f, q1 = 0.f;
    int g = g_batch[n0], cnt = 0;
    for (int n = n0; n < nend; n++) {
        const int gn = g_batch[n];
        if (gn != g) {
            atomicAdd(&g_sum[g * DIM + d0], s0);
            atomicAdd(&g_sum[g * DIM + d1], s1);
            atomicAdd(&g_sq [g * DIM + d0], q0);
            atomicAdd(&g_sq [g * DIM + d1], q1);
            if (t == 0) atomicAdd(&g_cnt[g], (float)cnt);
            s0 = s1 = q0 = q1 = 0.f; cnt = 0; g = gn;
        }
        const float* row = g_acc + (size_t)n * DIM;
        const float x0 = row[d0], x1 = row[d1];
        s0 += x0; s1 += x1; q0 += x0 * x0; q1 += x1 * x1; cnt++;
    }
    atomicAdd(&g_sum[g * DIM + d0], s0);
    atomicAdd(&g_sum[g * DIM + d1], s1);
    atomicAdd(&g_sq [g * DIM + d0], q0);
    atomicAdd(&g_sq [g * DIM + d1], q1);
    if (t == 0) atomicAdd(&g_cnt[g], (float)cnt);
}

// ---------------------------------------------------------------- finalize: normalize + relu
__global__ __launch_bounds__(256) void k_final(const float* __restrict__ gw,
                                               const float* __restrict__ gb,
                                               const float* __restrict__ ms,
                                               float* __restrict__ out) {
    const int idx = blockIdx.x * blockDim.x + threadIdx.x;
    if (idx >= N_NODES * (DIM / 4)) return;
    const int n = idx >> 7;
    const int dc = (idx & 127) << 2;
    const int g = g_batch[n];
    const float ic = 1.f / fmaxf(g_cnt[g], 1.f);
    const float4 x  = *(const float4*)(g_acc + (size_t)n * DIM + dc);
    const float4 sm = *(const float4*)(g_sum + g * DIM + dc);
    const float4 sq = *(const float4*)(g_sq  + g * DIM + dc);
    const float4 w4 = *(const float4*)(gw + dc);
    const float4 b4 = *(const float4*)(gb + dc);
    const float4 m4 = *(const float4*)(ms + dc);
    float4 o;
    {
        const float m = sm.x * ic, c = m * m4.x;
        const float var = sq.x * ic - 2.f * c * m + c * c;
        o.x = fmaxf(w4.x * (x.x - c) * rsqrtf(var + EPSV) + b4.x, 0.f);
    }
    {
        const float m = sm.y * ic, c = m * m4.y;
        const float var = sq.y * ic - 2.f * c * m + c * c;
        o.y = fmaxf(w4.y * (x.y - c) * rsqrtf(var + EPSV) + b4.y, 0.f);
    }
    {
        const float m = sm.z * ic, c = m * m4.z;
        const float var = sq.z * ic - 2.f * c * m + c * c;
        o.z = fmaxf(w4.z * (x.z - c) * rsqrtf(var + EPSV) + b4.z, 0.f);
    }
    {
        const float m = sm.w * ic, c = m * m4.w;
        const float var = sq.w * ic - 2.f * c * m + c * c;
        o.w = fmaxf(w4.w * (x.w - c) * rsqrtf(var + EPSV) + b4.w, 0.f);
    }
    *(float4*)(out + (size_t)n * DIM + dc) = o;
}

// ---------------------------------------------------------------- launch
extern "C" void kernel_launch(void* const* d_in, const int* in_sizes, int n_in,
                              void* d_out, int out_size) {
    const float* node  = (const float*)d_in[0];
    const float* eattr = (const float*)d_in[1];
    const float* W     = (const float*)d_in[2];
    const float* b     = (const float*)d_in[3];
    const float* gw    = (const float*)d_in[4];
    const float* gb    = (const float*)d_in[5];
    const float* ms    = (const float*)d_in[6];
    const void*  ei    = d_in[7];
    const void*  batch = d_in[8];
    float* out = (float*)d_out;

    cudaFuncSetAttribute(k_gemm, cudaFuncAttributeMaxDynamicSharedMemorySize, SMEM_BYTES);

    k_init<<<(N_NODES + 255) / 256, 256>>>();
    k_convert<<<(N_EDGES + 255) / 256, 256>>>(ei, batch, eattr);
    {
        dim3 grid(DIM / 256, (N_NODES + 127) / 128);   // (2, 391)
        k_gemm<<<grid, 512, SMEM_BYTES>>>(node, W, b);
    }
    k_scatter<<<N_EDGES, 128>>>(eattr);
    k_stats<<<(N_NODES + 127) / 128, 256>>>();
    k_final<<<(N_NODES * (DIM / 4) + 255) / 256, 256>>>(gw, gb, ms, out);
}

// round 7
// speedup vs baseline: 1.2972x; 1.0080x over previous
#include <cuda_runtime.h>
#include <cstdint>

#define N_NODES 50000
#define N_EDGES 160000
#define DIM     512
#define N_GRAPHS 64
#define EPSV    1e-5f

// GEMM tiling: BM=128, BN=256, BK=32, 3-stage cp.async, 16 warps, warp tile 64x32
#define AS_STR 36
#define BS_STR 264
#define AS_ELE (128 * AS_STR)
#define BS_ELE (32 * BS_STR)
#define NSTAGE 3
#define SMEM_BYTES (NSTAGE * (AS_ELE + BS_ELE) * 4)   // 156672 B

// scatter slicing: 4 slices of 128 floats (512B)
#define NSLICE 4
#define SLICE_F (DIM / NSLICE)     // 128 floats
#define EDGES_PER_BLK 8

// ---- scratch (static __device__: allocation-free) ----
__device__ float g_xw [(size_t)N_NODES * DIM];
__device__ float g_acc[(size_t)N_NODES * DIM];
__device__ float g_deg[N_NODES];
__device__ float g_coef[N_EDGES];
__device__ float g_sum[N_GRAPHS * DIM];
__device__ float g_sq [N_GRAPHS * DIM];
__device__ float g_cnt[N_GRAPHS];
__device__ int   g_ei_row[N_EDGES];
__device__ int   g_ei_col[N_EDGES];
__device__ int   g_batch [N_NODES];

// ---------------------------------------------------------------- init
__global__ void k_init() {
    int i = blockIdx.x * blockDim.x + threadIdx.x;
    if (i < N_NODES) g_deg[i] = 1.0f;               // self-loop weight
    if (i < N_GRAPHS * DIM) { g_sum[i] = 0.f; g_sq[i] = 0.f; }
    if (i < N_GRAPHS) g_cnt[i] = 0.f;
}

// ---------------------------------------------------------------- dtype-robust index conversion + degree
__global__ void k_convert(const void* __restrict__ ei, const void* __restrict__ batch,
                          const float* __restrict__ w) {
    __shared__ int s64;
    const int tid = threadIdx.x;
    if (tid == 0) {
        const long long* q = (const long long*)ei;
        int ok = 1;
#pragma unroll
        for (int i = 0; i < 8; i++) { long long v = q[i]; if (v < 0 || v >= N_NODES) ok = 0; }
        s64 = ok;
    }
    __syncthreads();
    const int is64 = s64;
    const int e = blockIdx.x * blockDim.x + tid;
    if (e < N_EDGES) {
        int r, c;
        if (is64) { r = (int)((const long long*)ei)[e]; c = (int)((const long long*)ei)[N_EDGES + e]; }
        else      { r = ((const int*)ei)[e];            c = ((const int*)ei)[N_EDGES + e]; }
        r = min(max(r, 0), N_NODES - 1);
        c = min(max(c, 0), N_NODES - 1);
        g_ei_row[e] = r;
        g_ei_col[e] = c;
        atomicAdd(&g_deg[c], w[e]);
    }
    if (e < N_NODES) {
        int bv = is64 ? (int)((const long long*)batch)[e] : ((const int*)batch)[e];
        g_batch[e] = min(max(bv, 0), N_GRAPHS - 1);
    }
}

// ---------------------------------------------------------------- per-edge coefficient (after deg final)
__global__ void k_coef(const float* __restrict__ w) {
    const int e = blockIdx.x * blockDim.x + threadIdx.x;
    if (e < N_EDGES)
        g_coef[e] = w[e] * rsqrtf(g_deg[g_ei_row[e]]) * rsqrtf(g_deg[g_ei_col[e]]);
}

// ---------------------------------------------------------------- helpers
__device__ __forceinline__ void cpasync16(uint32_t dst, const void* src) {
    asm volatile("cp.async.cg.shared.global [%0], [%1], 16;" :: "r"(dst), "l"(src));
}
#define CP_COMMIT()  asm volatile("cp.async.commit_group;" ::: "memory")
#define CP_WAIT(n)   asm volatile("cp.async.wait_group %0;" :: "n"(n) : "memory")
__device__ __forceinline__ uint32_t smem_u32(const void* p) {
    uint32_t a;
    asm("{ .reg .u64 t; cvta.to.shared.u64 t, %1; cvt.u32.u64 %0, t; }" : "=r"(a) : "l"(p));
    return a;
}
__device__ __forceinline__ void mma_tf32(float* d, const uint32_t* a, const uint32_t* b) {
    asm volatile(
        "mma.sync.aligned.m16n8k8.row.col.f32.tf32.tf32.f32 "
        "{%0,%1,%2,%3},{%4,%5,%6,%7},{%8,%9},{%0,%1,%2,%3};\n"
        : "+f"(d[0]), "+f"(d[1]), "+f"(d[2]), "+f"(d[3])
        : "r"(a[0]), "r"(a[1]), "r"(a[2]), "r"(a[3]), "r"(b[0]), "r"(b[1]));
}

// ---------------------------------------------------------------- GEMM + fused epilogue
__global__ void __launch_bounds__(512, 1) k_gemm(
    const float* __restrict__ A,
    const float* __restrict__ B,
    const float* __restrict__ bias)
{
    extern __shared__ float smem[];
    const uint32_t sbase = smem_u32(smem);
    const int tid  = threadIdx.x;
    const int lane = tid & 31;
    const int warp = tid >> 5;
    const int wm = warp >> 3;   // 0..1
    const int wn = warp & 7;    // 0..7
    const int m0 = blockIdx.y * 128;
    const int n0 = blockIdx.x * 256;

    float acc[4][4][4];
#pragma unroll
    for (int i = 0; i < 4; i++)
#pragma unroll
        for (int j = 0; j < 4; j++)
#pragma unroll
            for (int c = 0; c < 4; c++) acc[i][j][c] = 0.f;

#define ISSUE(KT) do {                                                           \
        const int kk = (KT) * 32;                                                \
        const uint32_t sa = sbase + ((KT) % NSTAGE) * (AS_ELE * 4);              \
        const uint32_t sbb = sbase + (NSTAGE * AS_ELE + ((KT) % NSTAGE) * BS_ELE) * 4; \
        _Pragma("unroll")                                                        \
        for (int i = 0; i < 2; i++) {                                            \
            const int idx = tid + i * 512;                                       \
            const int row = idx >> 3, col = (idx & 7) * 4;                       \
            int gm = m0 + row;                                                   \
            if (gm >= N_NODES) gm = N_NODES - 1;                                 \
            cpasync16(sa + (uint32_t)(row * AS_STR + col) * 4,                   \
                      A + (size_t)gm * 512 + kk + col);                          \
        }                                                                        \
        _Pragma("unroll")                                                        \
        for (int i = 0; i < 4; i++) {                                            \
            const int idx = tid + i * 512;                                       \
            const int row = idx >> 6, col = (idx & 63) * 4;                      \
            cpasync16(sbb + (uint32_t)(row * BS_STR + col) * 4,                  \
                      B + (size_t)(kk + row) * 512 + n0 + col);                  \
        }                                                                        \
        CP_COMMIT();                                                             \
    } while (0)

    ISSUE(0);
    ISSUE(1);

#pragma unroll 1
    for (int kt = 0; kt < 16; kt++) {
        CP_WAIT(1);
        __syncthreads();
        if (kt + 2 < 16) ISSUE(kt + 2);

        const float* as = smem + (kt % NSTAGE) * AS_ELE;
        const float* bs = smem + NSTAGE * AS_ELE + (kt % NSTAGE) * BS_ELE;
#pragma unroll
        for (int ks = 0; ks < 4; ks++) {
            uint32_t af[4][4], bf[4][2];
            const int kk = ks * 8 + (lane & 3);
#pragma unroll
            for (int i = 0; i < 4; i++) {
                const int r = wm * 64 + i * 16 + (lane >> 2);
                af[i][0] = __float_as_uint(as[r * AS_STR + kk]);
                af[i][1] = __float_as_uint(as[(r + 8) * AS_STR + kk]);
                af[i][2] = __float_as_uint(as[r * AS_STR + kk + 4]);
                af[i][3] = __float_as_uint(as[(r + 8) * AS_STR + kk + 4]);
            }
#pragma unroll
            for (int j = 0; j < 4; j++) {
                const int c = wn * 32 + j * 8 + (lane >> 2);
                bf[j][0] = __float_as_uint(bs[kk * BS_STR + c]);
                bf[j][1] = __float_as_uint(bs[(kk + 4) * BS_STR + c]);
            }
#pragma unroll
            for (int i = 0; i < 4; i++)
#pragma unroll
                for (int j = 0; j < 4; j++)
                    mma_tf32(acc[i][j], af[i], bf[j]);
        }
    }

    // epilogue
#pragma unroll
    for (int i = 0; i < 4; i++) {
        const int rbase = m0 + wm * 64 + i * 16 + (lane >> 2);
#pragma unroll
        for (int h = 0; h < 2; h++) {
            const int gm = rbase + h * 8;
            if (gm < N_NODES) {
                const float invdeg = 1.0f / g_deg[gm];
#pragma unroll
                for (int j = 0; j < 4; j++) {
                    const int cb = n0 + wn * 32 + j * 8 + ((lane & 3) << 1);
                    const size_t o = (size_t)gm * 512 + cb;
                    const float v0 = acc[i][j][h * 2 + 0];
                    const float v1 = acc[i][j][h * 2 + 1];
                    *(float2*)(g_xw + o) = make_float2(v0, v1);
                    const float2 a2 = *(const float2*)(A + o);
                    const float2 b2 = *(const float2*)(bias + cb);
                    *(float2*)(g_acc + o) = make_float2(a2.x + b2.x + v0 * invdeg,
                                                        a2.y + b2.y + v1 * invdeg);
                }
            }
        }
    }
#undef ISSUE
}

// ---------------------------------------------------------------- edge scatter (feature-sliced)
// one warp per edge, 512B slice; sequential launches keep the per-slice
// working set (25MB src + 25MB dst) L2-resident.
__global__ __launch_bounds__(256) void k_scatter(int slice) {
    const int e = blockIdx.x * EDGES_PER_BLK + (threadIdx.x >> 5);
    if (e >= N_EDGES) return;
    const int t = threadIdx.x & 31;
    const int r = g_ei_row[e];
    const int c = g_ei_col[e];
    const float coef = g_coef[e];
    const float4* src = (const float4*)(g_xw + (size_t)r * DIM + slice * SLICE_F);
    float4* dst = (float4*)(g_acc + (size_t)c * DIM + slice * SLICE_F);
    const float4 v = src[t];
    asm volatile("red.global.add.v4.f32 [%0], {%1,%2,%3,%4};"
                 :: "l"(dst + t), "f"(v.x * coef), "f"(v.y * coef),
                    "f"(v.z * coef), "f"(v.w * coef)
                 : "memory");
}

// ---------------------------------------------------------------- GraphNorm stats (single pass)
__global__ __launch_bounds__(256) void k_stats() {
    const int n0 = blockIdx.x * 128;
    const int nend = min(n0 + 128, N_NODES);
    const int t = threadIdx.x;
    const int d0 = t, d1 = t + 256;
    float s0 = 0.f, s1 = 0.f, q0 = 0.f, q1 = 0.f;
    int g = g_batch[n0], cnt = 0;
    for (int n = n0; n < nend; n++) {
        const int gn = g_batch[n];
        if (gn != g) {
            atomicAdd(&g_sum[g * DIM + d0], s0);
            atomicAdd(&g_sum[g * DIM + d1], s1);
            atomicAdd(&g_sq [g * DIM + d0], q0);
            atomicAdd(&g_sq [g * DIM + d1], q1);
            if (t == 0) atomicAdd(&g_cnt[g], (float)cnt);
            s0 = s1 = q0 = q1 = 0.f; cnt = 0; g = gn;
        }
        const float* row = g_acc + (size_t)n * DIM;
        const float x0 = row[d0], x1 = row[d1];
        s0 += x0; s1 += x1; q0 += x0 * x0; q1 += x1 * x1; cnt++;
    }
    atomicAdd(&g_sum[g * DIM + d0], s0);
    atomicAdd(&g_sum[g * DIM + d1], s1);
    atomicAdd(&g_sq [g * DIM + d0], q0);
    atomicAdd(&g_sq [g * DIM + d1], q1);
    if (t == 0) atomicAdd(&g_cnt[g], (float)cnt);
}

// ---------------------------------------------------------------- finalize: normalize + relu
__global__ __launch_bounds__(256) void k_final(const float* __restrict__ gw,
                                               const float* __restrict__ gb,
                                               const float* __restrict__ ms,
                                               float* __restrict__ out) {
    const int idx = blockIdx.x * blockDim.x + threadIdx.x;
    if (idx >= N_NODES * (DIM / 4)) return;
    const int n = idx >> 7;
    const int dc = (idx & 127) << 2;
    const int g = g_batch[n];
    const float ic = 1.f / fmaxf(g_cnt[g], 1.f);
    const float4 x  = *(const float4*)(g_acc + (size_t)n * DIM + dc);
    const float4 sm = *(const float4*)(g_sum + g * DIM + dc);
    const float4 sq = *(const float4*)(g_sq  + g * DIM + dc);
    const float4 w4 = *(const float4*)(gw + dc);
    const float4 b4 = *(const float4*)(gb + dc);
    const float4 m4 = *(const float4*)(ms + dc);
    float4 o;
    {
        const float m = sm.x * ic, c = m * m4.x;
        const float var = sq.x * ic - 2.f * c * m + c * c;
        o.x = fmaxf(w4.x * (x.x - c) * rsqrtf(var + EPSV) + b4.x, 0.f);
    }
    {
        const float m = sm.y * ic, c = m * m4.y;
        const float var = sq.y * ic - 2.f * c * m + c * c;
        o.y = fmaxf(w4.y * (x.y - c) * rsqrtf(var + EPSV) + b4.y, 0.f);
    }
    {
        const float m = sm.z * ic, c = m * m4.z;
        const float var = sq.z * ic - 2.f * c * m + c * c;
        o.z = fmaxf(w4.z * (x.z - c) * rsqrtf(var + EPSV) + b4.z, 0.f);
    }
    {
        const float m = sm.w * ic, c = m * m4.w;
        const float var = sq.w * ic - 2.f * c * m + c * c;
        o.w = fmaxf(w4.w * (x.w - c) * rsqrtf(var + EPSV) + b4.w, 0.f);
    }
    *(float4*)(out + (size_t)n * DIM + dc) = o;
}

// ---------------------------------------------------------------- launch
extern "C" void kernel_launch(void* const* d_in, const int* in_sizes, int n_in,
                              void* d_out, int out_size) {
    const float* node  = (const float*)d_in[0];
    const float* eattr = (const float*)d_in[1];
    const float* W     = (const float*)d_in[2];
    const float* b     = (const float*)d_in[3];
    const float* gw    = (const float*)d_in[4];
    const float* gb    = (const float*)d_in[5];
    const float* ms    = (const float*)d_in[6];
    const void*  ei    = d_in[7];
    const void*  batch = d_in[8];
    float* out = (float*)d_out;

    cudaFuncSetAttribute(k_gemm, cudaFuncAttributeMaxDynamicSharedMemorySize, SMEM_BYTES);

    k_init<<<(N_NODES + 255) / 256, 256>>>();
    k_convert<<<(N_EDGES + 255) / 256, 256>>>(ei, batch, eattr);
    k_coef<<<(N_EDGES + 255) / 256, 256>>>(eattr);
    {
        dim3 grid(DIM / 256, (N_NODES + 127) / 128);   // (2, 391)
        k_gemm<<<grid, 512, SMEM_BYTES>>>(node, W, b);
    }
    {
        const int blocks = (N_EDGES + EDGES_PER_BLK - 1) / EDGES_PER_BLK;
        for (int s = 0; s < NSLICE; s++)
            k_scatter<<<blocks, 256>>>(s);
    }
    k_stats<<<(N_NODES + 127) / 128, 256>>>();
    k_final<<<(N_NODES * (DIM / 4) + 255) / 256, 256>>>(gw, gb, ms, out);
}

// round 8
// speedup vs baseline: 1.3959x; 1.0761x over previous
#include <cuda_runtime.h>
#include <cstdint>

#define N_NODES 50000
#define N_EDGES 160000
#define DIM     512
#define N_GRAPHS 64
#define EPSV    1e-5f

// GEMM tiling: BM=128, BN=128, BK=32, 3-stage cp.async, 8 warps, warp tile 64x32,
// 2 CTAs/SM (independent barrier domains hide stage-boundary stalls)
#define AS_STR 36
#define BS_STR 136
#define AS_ELE (128 * AS_STR)          // 4608 floats/stage
#define BS_ELE (32 * BS_STR)           // 4352 floats/stage
#define NSTAGE 3
#define SMEM_BYTES (NSTAGE * (AS_ELE + BS_ELE) * 4)   // 107520 B

// scatter slicing: 4 slices of 128 floats (512B)
#define NSLICE 4
#define SLICE_F (DIM / NSLICE)
#define EDGES_PER_BLK 8

// ---- scratch (static __device__: allocation-free) ----
__device__ float g_xw [(size_t)N_NODES * DIM];
__device__ float g_acc[(size_t)N_NODES * DIM];
__device__ float g_deg[N_NODES];
__device__ float g_coef[N_EDGES];
__device__ float g_sum[N_GRAPHS * DIM];
__device__ float g_sq [N_GRAPHS * DIM];
__device__ float g_cnt[N_GRAPHS];
__device__ int   g_ei_row[N_EDGES];
__device__ int   g_ei_col[N_EDGES];
__device__ int   g_batch [N_NODES];

// ---------------------------------------------------------------- init
__global__ void k_init() {
    int i = blockIdx.x * blockDim.x + threadIdx.x;
    if (i < N_NODES) g_deg[i] = 1.0f;
    if (i < N_GRAPHS * DIM) { g_sum[i] = 0.f; g_sq[i] = 0.f; }
    if (i < N_GRAPHS) g_cnt[i] = 0.f;
}

// ---------------------------------------------------------------- dtype-robust index conversion + degree
__global__ void k_convert(const void* __restrict__ ei, const void* __restrict__ batch,
                          const float* __restrict__ w) {
    __shared__ int s64;
    const int tid = threadIdx.x;
    if (tid == 0) {
        const long long* q = (const long long*)ei;
        int ok = 1;
#pragma unroll
        for (int i = 0; i < 8; i++) { long long v = q[i]; if (v < 0 || v >= N_NODES) ok = 0; }
        s64 = ok;
    }
    __syncthreads();
    const int is64 = s64;
    const int e = blockIdx.x * blockDim.x + tid;
    if (e < N_EDGES) {
        int r, c;
        if (is64) { r = (int)((const long long*)ei)[e]; c = (int)((const long long*)ei)[N_EDGES + e]; }
        else      { r = ((const int*)ei)[e];            c = ((const int*)ei)[N_EDGES + e]; }
        r = min(max(r, 0), N_NODES - 1);
        c = min(max(c, 0), N_NODES - 1);
        g_ei_row[e] = r;
        g_ei_col[e] = c;
        atomicAdd(&g_deg[c], w[e]);
    }
    if (e < N_NODES) {
        int bv = is64 ? (int)((const long long*)batch)[e] : ((const int*)batch)[e];
        g_batch[e] = min(max(bv, 0), N_GRAPHS - 1);
    }
}

// ---------------------------------------------------------------- per-edge coefficient
__global__ void k_coef(const float* __restrict__ w) {
    const int e = blockIdx.x * blockDim.x + threadIdx.x;
    if (e < N_EDGES)
        g_coef[e] = w[e] * rsqrtf(g_deg[g_ei_row[e]]) * rsqrtf(g_deg[g_ei_col[e]]);
}

// ---------------------------------------------------------------- helpers
__device__ __forceinline__ void cpasync16(uint32_t dst, const void* src) {
    asm volatile("cp.async.cg.shared.global [%0], [%1], 16;" :: "r"(dst), "l"(src));
}
#define CP_COMMIT()  asm volatile("cp.async.commit_group;" ::: "memory")
#define CP_WAIT(n)   asm volatile("cp.async.wait_group %0;" :: "n"(n) : "memory")
__device__ __forceinline__ uint32_t smem_u32(const void* p) {
    uint32_t a;
    asm("{ .reg .u64 t; cvta.to.shared.u64 t, %1; cvt.u32.u64 %0, t; }" : "=r"(a) : "l"(p));
    return a;
}
__device__ __forceinline__ void mma_tf32(float* d, const uint32_t* a, const uint32_t* b) {
    asm volatile(
        "mma.sync.aligned.m16n8k8.row.col.f32.tf32.tf32.f32 "
        "{%0,%1,%2,%3},{%4,%5,%6,%7},{%8,%9},{%0,%1,%2,%3};\n"
        : "+f"(d[0]), "+f"(d[1]), "+f"(d[2]), "+f"(d[3])
        : "r"(a[0]), "r"(a[1]), "r"(a[2]), "r"(a[3]), "r"(b[0]), "r"(b[1]));
}

// ---------------------------------------------------------------- GEMM + fused epilogue
// C = node @ W, tf32 mma.sync.  256 threads / 8 warps (2x4), warp tile 64x32,
// BM=128 BN=128 BK=32, 3-stage cp.async, 2 CTAs/SM.
__global__ void __launch_bounds__(256, 2) k_gemm(
    const float* __restrict__ A,
    const float* __restrict__ B,
    const float* __restrict__ bias)
{
    extern __shared__ float smem[];
    const uint32_t sbase = smem_u32(smem);
    const int tid  = threadIdx.x;
    const int lane = tid & 31;
    const int warp = tid >> 5;
    const int wm = warp >> 2;   // 0..1
    const int wn = warp & 3;    // 0..3
    const int m0 = blockIdx.y * 128;
    const int n0 = blockIdx.x * 128;

    float acc[4][4][4];
#pragma unroll
    for (int i = 0; i < 4; i++)
#pragma unroll
        for (int j = 0; j < 4; j++)
#pragma unroll
            for (int c = 0; c < 4; c++) acc[i][j][c] = 0.f;

#define ISSUE(KT) do {                                                           \
        const int kk = (KT) * 32;                                                \
        const uint32_t sa = sbase + ((KT) % NSTAGE) * (AS_ELE * 4);              \
        const uint32_t sbb = sbase + (NSTAGE * AS_ELE + ((KT) % NSTAGE) * BS_ELE) * 4; \
        _Pragma("unroll")                                                        \
        for (int i = 0; i < 4; i++) {                                            \
            const int idx = tid + i * 256;                                       \
            const int row = idx >> 3, col = (idx & 7) * 4;                       \
            int gm = m0 + row;                                                   \
            if (gm >= N_NODES) gm = N_NODES - 1;                                 \
            cpasync16(sa + (uint32_t)(row * AS_STR + col) * 4,                   \
                      A + (size_t)gm * 512 + kk + col);                          \
        }                                                                        \
        _Pragma("unroll")                                                        \
        for (int i = 0; i < 4; i++) {                                            \
            const int idx = tid + i * 256;                                       \
            const int row = idx >> 5, col = (idx & 31) * 4;                      \
            cpasync16(sbb + (uint32_t)(row * BS_STR + col) * 4,                  \
                      B + (size_t)(kk + row) * 512 + n0 + col);                  \
        }                                                                        \
        CP_COMMIT();                                                             \
    } while (0)

    ISSUE(0);
    ISSUE(1);

#pragma unroll 1
    for (int kt = 0; kt < 16; kt++) {
        CP_WAIT(1);
        __syncthreads();
        if (kt + 2 < 16) ISSUE(kt + 2);

        const float* as = smem + (kt % NSTAGE) * AS_ELE;
        const float* bs = smem + NSTAGE * AS_ELE + (kt % NSTAGE) * BS_ELE;
#pragma unroll
        for (int ks = 0; ks < 4; ks++) {
            uint32_t af[4][4], bf[4][2];
            const int kk = ks * 8 + (lane & 3);
#pragma unroll
            for (int i = 0; i < 4; i++) {
                const int r = wm * 64 + i * 16 + (lane >> 2);
                af[i][0] = __float_as_uint(as[r * AS_STR + kk]);
                af[i][1] = __float_as_uint(as[(r + 8) * AS_STR + kk]);
                af[i][2] = __float_as_uint(as[r * AS_STR + kk + 4]);
                af[i][3] = __float_as_uint(as[(r + 8) * AS_STR + kk + 4]);
            }
#pragma unroll
            for (int j = 0; j < 4; j++) {
                const int c = wn * 32 + j * 8 + (lane >> 2);
                bf[j][0] = __float_as_uint(bs[kk * BS_STR + c]);
                bf[j][1] = __float_as_uint(bs[(kk + 4) * BS_STR + c]);
            }
#pragma unroll
            for (int i = 0; i < 4; i++)
#pragma unroll
                for (int j = 0; j < 4; j++)
                    mma_tf32(acc[i][j], af[i], bf[j]);
        }
    }

    // epilogue
#pragma unroll
    for (int i = 0; i < 4; i++) {
        const int rbase = m0 + wm * 64 + i * 16 + (lane >> 2);
#pragma unroll
        for (int h = 0; h < 2; h++) {
            const int gm = rbase + h * 8;
            if (gm < N_NODES) {
                const float invdeg = 1.0f / g_deg[gm];
#pragma unroll
                for (int j = 0; j < 4; j++) {
                    const int cb = n0 + wn * 32 + j * 8 + ((lane & 3) << 1);
                    const size_t o = (size_t)gm * 512 + cb;
                    const float v0 = acc[i][j][h * 2 + 0];
                    const float v1 = acc[i][j][h * 2 + 1];
                    *(float2*)(g_xw + o) = make_float2(v0, v1);
                    const float2 a2 = *(const float2*)(A + o);
                    const float2 b2 = *(const float2*)(bias + cb);
                    *(float2*)(g_acc + o) = make_float2(a2.x + b2.x + v0 * invdeg,
                                                        a2.y + b2.y + v1 * invdeg);
                }
            }
        }
    }
#undef ISSUE
}

// ---------------------------------------------------------------- edge scatter (feature-sliced)
__global__ __launch_bounds__(256) void k_scatter(int slice) {
    const int e = blockIdx.x * EDGES_PER_BLK + (threadIdx.x >> 5);
    if (e >= N_EDGES) return;
    const int t = threadIdx.x & 31;
    const int r = g_ei_row[e];
    const int c = g_ei_col[e];
    const float coef = g_coef[e];
    const float4* src = (const float4*)(g_xw + (size_t)r * DIM + slice * SLICE_F);
    float4* dst = (float4*)(g_acc + (size_t)c * DIM + slice * SLICE_F);
    const float4 v = src[t];
    asm volatile("red.global.add.v4.f32 [%0], {%1,%2,%3,%4};"
                 :: "l"(dst + t), "f"(v.x * coef), "f"(v.y * coef),
                    "f"(v.z * coef), "f"(v.w * coef)
                 : "memory");
}

// ---------------------------------------------------------------- GraphNorm stats (single pass)
__global__ __launch_bounds__(256) void k_stats() {
    const int n0 = blockIdx.x * 128;
    const int nend = min(n0 + 128, N_NODES);
    const int t = threadIdx.x;
    const int d0 = t, d1 = t + 256;
    float s0 = 0.f, s1 = 0.f, q0 = 0.f, q1 = 0.f;
    int g = g_batch[n0], cnt = 0;
    for (int n = n0; n < nend; n++) {
        const int gn = g_batch[n];
        if (gn != g) {
            atomicAdd(&g_sum[g * DIM + d0], s0);
            atomicAdd(&g_sum[g * DIM + d1], s1);
            atomicAdd(&g_sq [g * DIM + d0], q0);
            atomicAdd(&g_sq [g * DIM + d1], q1);
            if (t == 0) atomicAdd(&g_cnt[g], (float)cnt);
            s0 = s1 = q0 = q1 = 0.f; cnt = 0; g = gn;
        }
        const float* row = g_acc + (size_t)n * DIM;
        const float x0 = row[d0], x1 = row[d1];
        s0 += x0; s1 += x1; q0 += x0 * x0; q1 += x1 * x1; cnt++;
    }
    atomicAdd(&g_sum[g * DIM + d0], s0);
    atomicAdd(&g_sum[g * DIM + d1], s1);
    atomicAdd(&g_sq [g * DIM + d0], q0);
    atomicAdd(&g_sq [g * DIM + d1], q1);
    if (t == 0) atomicAdd(&g_cnt[g], (float)cnt);
}

// ---------------------------------------------------------------- finalize: normalize + relu
__global__ __launch_bounds__(256) void k_final(const float* __restrict__ gw,
                                               const float* __restrict__ gb,
                                               const float* __restrict__ ms,
                                               float* __restrict__ out) {
    const int idx = blockIdx.x * blockDim.x + threadIdx.x;
    if (idx >= N_NODES * (DIM / 4)) return;
    const int n = idx >> 7;
    const int dc = (idx & 127) << 2;
    const int g = g_batch[n];
    const float ic = 1.f / fmaxf(g_cnt[g], 1.f);
    const float4 x  = *(const float4*)(g_acc + (size_t)n * DIM + dc);
    const float4 sm = *(const float4*)(g_sum + g * DIM + dc);
    const float4 sq = *(const float4*)(g_sq  + g * DIM + dc);
    const float4 w4 = *(const float4*)(gw + dc);
    const float4 b4 = *(const float4*)(gb + dc);
    const float4 m4 = *(const float4*)(ms + dc);
    float4 o;
    {
        const float m = sm.x * ic, c = m * m4.x;
        const float var = sq.x * ic - 2.f * c * m + c * c;
        o.x = fmaxf(w4.x * (x.x - c) * rsqrtf(var + EPSV) + b4.x, 0.f);
    }
    {
        const float m = sm.y * ic, c = m * m4.y;
        const float var = sq.y * ic - 2.f * c * m + c * c;
        o.y = fmaxf(w4.y * (x.y - c) * rsqrtf(var + EPSV) + b4.y, 0.f);
    }
    {
        const float m = sm.z * ic, c = m * m4.z;
        const float var = sq.z * ic - 2.f * c * m + c * c;
        o.z = fmaxf(w4.z * (x.z - c) * rsqrtf(var + EPSV) + b4.z, 0.f);
    }
    {
        const float m = sm.w * ic, c = m * m4.w;
        const float var = sq.w * ic - 2.f * c * m + c * c;
        o.w = fmaxf(w4.w * (x.w - c) * rsqrtf(var + EPSV) + b4.w, 0.f);
    }
    *(float4*)(out + (size_t)n * DIM + dc) = o;
}

// ---------------------------------------------------------------- launch
extern "C" void kernel_launch(void* const* d_in, const int* in_sizes, int n_in,
                              void* d_out, int out_size) {
    const float* node  = (const float*)d_in[0];
    const float* eattr = (const float*)d_in[1];
    const float* W     = (const float*)d_in[2];
    const float* b     = (const float*)d_in[3];
    const float* gw    = (const float*)d_in[4];
    const float* gb    = (const float*)d_in[5];
    const float* ms    = (const float*)d_in[6];
    const void*  ei    = d_in[7];
    const void*  batch = d_in[8];
    float* out = (float*)d_out;

    cudaFuncSetAttribute(k_gemm, cudaFuncAttributeMaxDynamicSharedMemorySize, SMEM_BYTES);

    k_init<<<(N_NODES + 255) / 256, 256>>>();
    k_convert<<<(N_EDGES + 255) / 256, 256>>>(ei, batch, eattr);
    k_coef<<<(N_EDGES + 255) / 256, 256>>>(eattr);
    {
        dim3 grid(DIM / 128, (N_NODES + 127) / 128);   // (4, 391)
        k_gemm<<<grid, 256, SMEM_BYTES>>>(node, W, b);
    }
    {
        const int blocks = (N_EDGES + EDGES_PER_BLK - 1) / EDGES_PER_BLK;
        for (int s = 0; s < NSLICE; s++)
            k_scatter<<<blocks, 256>>>(s);
    }
    k_stats<<<(N_NODES + 127) / 128, 256>>>();
    k_final<<<(N_NODES * (DIM / 4) + 255) / 256, 256>>>(gw, gb, ms, out);
}